// round 1
// baseline (speedup 1.0000x reference)
#include <cuda_runtime.h>
#include <cuda_bf16.h>
#include <math_constants.h>

// Problem constants (from reference setup_inputs)
#define BQ  16
#define C   256
#define HW  1024          // 32*32
#define N   16384         // B*H*W
#define K   8192
#define TM  64            // query tile per block
#define TN  64            // code tile per k-iteration

// scratch: per-query argmin index, codebook row norms
__device__ int   g_idx[N];
__device__ float g_enorm[K];

// ---------------------------------------------------------------------------
// Kernel 1: ||e_k||^2 for all K codebook rows. One warp per row.
// ---------------------------------------------------------------------------
__global__ void enorm_kernel(const float* __restrict__ emb) {
    int k    = blockIdx.x * 8 + (threadIdx.x >> 5);
    int lane = threadIdx.x & 31;
    const float4* row = (const float4*)(emb + (size_t)k * C);
    float s = 0.f;
    #pragma unroll
    for (int i = 0; i < 2; i++) {
        float4 v = row[lane + 32 * i];
        s += v.x * v.x + v.y * v.y + v.z * v.z + v.w * v.w;
    }
    #pragma unroll
    for (int off = 16; off > 0; off >>= 1)
        s += __shfl_xor_sync(0xffffffffu, s, off);
    if (lane == 0) g_enorm[k] = s;
}

// ---------------------------------------------------------------------------
// Kernel 2: fused distance GEMM + argmin.
// Block: 256 threads (16x16). Block tile: 64 queries x 64 codes per k-iter,
// full C=256 in shared memory. Micro-tile 4x4 per thread.
//   zs_t : [C][TM]  z tile transposed (conflict-free stores & broadcast reads)
//   es   : [TN][C]  codebook tile, float4-XOR-swizzled for conflict-free reads
// Score = ||e||^2 - 2 z.e  (||z||^2 constant per row, irrelevant for argmin)
// ---------------------------------------------------------------------------
__global__ __launch_bounds__(256, 1)
void vq_argmin_kernel(const float* __restrict__ z,
                      const float* __restrict__ emb) {
    extern __shared__ float smem[];
    float* zs = smem;                 // C*TM floats (64 KB)
    float* es = smem + C * TM;        // TN*C floats (64 KB)

    const int tid = threadIdx.x;
    const int tx  = tid & 15;         // code micro-col  (codes 4*tx..4*tx+3)
    const int ty  = tid >> 4;         // query micro-row (queries 4*ty..4*ty+3)
    const int n0  = blockIdx.x * TM;

    // ---- load z tile, transposed to [c][q] --------------------------------
    {
        const int qq = tid & 63;
        const int cb = tid >> 6;      // 0..3
        const int n  = n0 + qq;
        const int b  = n >> 10;
        const int hw = n & 1023;
        const float* zb = z + (size_t)b * (C * HW) + hw;
        #pragma unroll 4
        for (int c0 = 0; c0 < C; c0 += 4) {
            int c = c0 + cb;
            zs[c * TM + qq] = zb[(size_t)c * HW];
        }
    }

    float minv[4];
    int   mini[4];
    #pragma unroll
    for (int i = 0; i < 4; i++) { minv[i] = CUDART_INF_F; mini[i] = 0; }

    const int sw = tx & 7;            // compute-side swizzle for this thread

    for (int k0 = 0; k0 < K; k0 += TN) {
        __syncthreads();              // es reuse barrier (also covers zs fill)

        // ---- load codebook tile, float4-swizzled --------------------------
        {
            const int c4  = tid & 63;
            const int kkb = tid >> 6;
            #pragma unroll
            for (int kk = kkb; kk < TN; kk += 4) {
                float4 v = *(const float4*)(emb + (size_t)(k0 + kk) * C + c4 * 4);
                int p = c4 ^ ((kk >> 2) & 7);
                *(float4*)(es + kk * C + p * 4) = v;
            }
        }
        __syncthreads();

        // ---- 64x64x256 micro-GEMM -----------------------------------------
        float acc[4][4] = {};
        #pragma unroll 2
        for (int c4 = 0; c4 < C / 4; c4++) {
            float4 aq[4];
            #pragma unroll
            for (int cc = 0; cc < 4; cc++)
                aq[cc] = *(const float4*)(zs + (c4 * 4 + cc) * TM + ty * 4);
            #pragma unroll
            for (int j = 0; j < 4; j++) {
                float4 bv = *(const float4*)(es + (4 * tx + j) * C + ((c4 ^ sw) << 2));
                acc[0][j] += aq[0].x * bv.x; acc[0][j] += aq[1].x * bv.y;
                acc[0][j] += aq[2].x * bv.z; acc[0][j] += aq[3].x * bv.w;
                acc[1][j] += aq[0].y * bv.x; acc[1][j] += aq[1].y * bv.y;
                acc[1][j] += aq[2].y * bv.z; acc[1][j] += aq[3].y * bv.w;
                acc[2][j] += aq[0].z * bv.x; acc[2][j] += aq[1].z * bv.y;
                acc[2][j] += aq[2].z * bv.z; acc[2][j] += aq[3].z * bv.w;
                acc[3][j] += aq[0].w * bv.x; acc[3][j] += aq[1].w * bv.y;
                acc[3][j] += aq[2].w * bv.z; acc[3][j] += aq[3].w * bv.w;
            }
        }

        // ---- running argmin (k ascending + strict < => first-min tiebreak)
        #pragma unroll
        for (int j = 0; j < 4; j++) {
            int kg = k0 + 4 * tx + j;
            float en = g_enorm[kg];
            #pragma unroll
            for (int i = 0; i < 4; i++) {
                float s = fmaf(-2.f, acc[i][j], en);
                if (s < minv[i]) { minv[i] = s; mini[i] = kg; }
            }
        }
    }

    // ---- cross-thread (tx) reduction per query ----------------------------
    __syncthreads();
    float* rv = smem;                         // [64][16]
    int*   ri = (int*)(smem + TM * 16);       // [64][16]
    #pragma unroll
    for (int i = 0; i < 4; i++) {
        int q = ty * 4 + i;
        rv[q * 16 + tx] = minv[i];
        ri[q * 16 + tx] = mini[i];
    }
    __syncthreads();
    if (tid < TM) {
        float bv = rv[tid * 16];
        int   bi = ri[tid * 16];
        #pragma unroll
        for (int t = 1; t < 16; t++) {
            float v  = rv[tid * 16 + t];
            int   ix = ri[tid * 16 + t];
            if (v < bv || (v == bv && ix < bi)) { bv = v; bi = ix; }
        }
        g_idx[n0 + tid] = bi;
    }
}

// ---------------------------------------------------------------------------
// Kernel 3: gather  out[b][c][h][w] = emb[idx[b*HW+hw]][c]
// gid == output linear index; consecutive lanes -> consecutive hw (coalesced
// out stores + coalesced idx loads; emb reads hit L2-resident 8.4 MB table).
// ---------------------------------------------------------------------------
__global__ void gather_kernel(const float* __restrict__ emb,
                              float* __restrict__ out) {
    int gid = blockIdx.x * blockDim.x + threadIdx.x;
    int hw  = gid & 1023;
    int c   = (gid >> 10) & 255;
    int b   = gid >> 18;
    int n   = (b << 10) | hw;
    out[gid] = emb[(size_t)g_idx[n] * C + c];
}

// ---------------------------------------------------------------------------
extern "C" void kernel_launch(void* const* d_in, const int* in_sizes, int n_in,
                              void* d_out, int out_size) {
    const float* z   = (const float*)d_in[0];   // [16,256,32,32]
    const float* emb = (const float*)d_in[1];   // [8192,256]
    float* out = (float*)d_out;                 // [16,256,32,32]

    static const size_t smem_bytes = (size_t)(C * TM + TN * C) * sizeof(float); // 128 KB
    cudaFuncSetAttribute(vq_argmin_kernel,
                         cudaFuncAttributeMaxDynamicSharedMemorySize,
                         (int)smem_bytes);

    enorm_kernel<<<K / 8, 256>>>(emb);
    vq_argmin_kernel<<<N / TM, 256, smem_bytes>>>(z, emb);
    gather_kernel<<<(N * C) / 256, 256>>>(emb, out);
}

// round 2
// speedup vs baseline: 1.0015x; 1.0015x over previous
#include <cuda_runtime.h>
#include <cuda_bf16.h>
#include <math_constants.h>

// Problem constants (from reference setup_inputs)
#define BQ  16
#define C   256
#define HW  1024          // 32*32
#define N   16384         // B*H*W
#define K   8192
#define TM  64            // query tile per block
#define TN  64            // code tile per k-iteration

// scratch: per-query argmin index, codebook row norms
__device__ int   g_idx[N];
__device__ float g_enorm[K];

// ---------------------------------------------------------------------------
// Kernel 1: ||e_k||^2 for all K codebook rows. One warp per row.
// ---------------------------------------------------------------------------
__global__ void enorm_kernel(const float* __restrict__ emb) {
    int k    = blockIdx.x * 8 + (threadIdx.x >> 5);
    int lane = threadIdx.x & 31;
    const float4* row = (const float4*)(emb + (size_t)k * C);
    float s = 0.f;
    #pragma unroll
    for (int i = 0; i < 2; i++) {
        float4 v = row[lane + 32 * i];
        s += v.x * v.x + v.y * v.y + v.z * v.z + v.w * v.w;
    }
    #pragma unroll
    for (int off = 16; off > 0; off >>= 1)
        s += __shfl_xor_sync(0xffffffffu, s, off);
    if (lane == 0) g_enorm[k] = s;
}

// ---------------------------------------------------------------------------
// Kernel 2: fused distance GEMM + argmin.
// Block: 256 threads (16x16). Block tile: 64 queries x 64 codes per k-iter,
// full C=256 in shared memory. Micro-tile 4x4 per thread.
//   zs_t : [C][TM]  z tile transposed (conflict-free stores & broadcast reads)
//   es   : [TN][C]  codebook tile, float4-XOR-swizzled for conflict-free reads
// Score = ||e||^2 - 2 z.e  (||z||^2 constant per row, irrelevant for argmin)
// ---------------------------------------------------------------------------
__global__ __launch_bounds__(256, 1)
void vq_argmin_kernel(const float* __restrict__ z,
                      const float* __restrict__ emb) {
    extern __shared__ float smem[];
    float* zs = smem;                 // C*TM floats (64 KB)
    float* es = smem + C * TM;        // TN*C floats (64 KB)

    const int tid = threadIdx.x;
    const int tx  = tid & 15;         // code micro-col  (codes 4*tx..4*tx+3)
    const int ty  = tid >> 4;         // query micro-row (queries 4*ty..4*ty+3)
    const int n0  = blockIdx.x * TM;

    // ---- load z tile, transposed to [c][q] --------------------------------
    {
        const int qq = tid & 63;
        const int cb = tid >> 6;      // 0..3
        const int n  = n0 + qq;
        const int b  = n >> 10;
        const int hw = n & 1023;
        const float* zb = z + (size_t)b * (C * HW) + hw;
        #pragma unroll 4
        for (int c0 = 0; c0 < C; c0 += 4) {
            int c = c0 + cb;
            zs[c * TM + qq] = zb[(size_t)c * HW];
        }
    }

    float minv[4];
    int   mini[4];
    #pragma unroll
    for (int i = 0; i < 4; i++) { minv[i] = CUDART_INF_F; mini[i] = 0; }

    const int sw = tx & 7;            // compute-side swizzle for this thread

    for (int k0 = 0; k0 < K; k0 += TN) {
        __syncthreads();              // es reuse barrier (also covers zs fill)

        // ---- load codebook tile, float4-swizzled --------------------------
        {
            const int c4  = tid & 63;
            const int kkb = tid >> 6;
            #pragma unroll
            for (int kk = kkb; kk < TN; kk += 4) {
                float4 v = *(const float4*)(emb + (size_t)(k0 + kk) * C + c4 * 4);
                int p = c4 ^ ((kk >> 2) & 7);
                *(float4*)(es + kk * C + p * 4) = v;
            }
        }
        __syncthreads();

        // ---- 64x64x256 micro-GEMM -----------------------------------------
        float acc[4][4] = {};
        #pragma unroll 2
        for (int c4 = 0; c4 < C / 4; c4++) {
            float4 aq[4];
            #pragma unroll
            for (int cc = 0; cc < 4; cc++)
                aq[cc] = *(const float4*)(zs + (c4 * 4 + cc) * TM + ty * 4);
            #pragma unroll
            for (int j = 0; j < 4; j++) {
                float4 bv = *(const float4*)(es + (4 * tx + j) * C + ((c4 ^ sw) << 2));
                acc[0][j] += aq[0].x * bv.x; acc[0][j] += aq[1].x * bv.y;
                acc[0][j] += aq[2].x * bv.z; acc[0][j] += aq[3].x * bv.w;
                acc[1][j] += aq[0].y * bv.x; acc[1][j] += aq[1].y * bv.y;
                acc[1][j] += aq[2].y * bv.z; acc[1][j] += aq[3].y * bv.w;
                acc[2][j] += aq[0].z * bv.x; acc[2][j] += aq[1].z * bv.y;
                acc[2][j] += aq[2].z * bv.z; acc[2][j] += aq[3].z * bv.w;
                acc[3][j] += aq[0].w * bv.x; acc[3][j] += aq[1].w * bv.y;
                acc[3][j] += aq[2].w * bv.z; acc[3][j] += aq[3].w * bv.w;
            }
        }

        // ---- running argmin (k ascending + strict < => first-min tiebreak)
        #pragma unroll
        for (int j = 0; j < 4; j++) {
            int kg = k0 + 4 * tx + j;
            float en = g_enorm[kg];
            #pragma unroll
            for (int i = 0; i < 4; i++) {
                float s = fmaf(-2.f, acc[i][j], en);
                if (s < minv[i]) { minv[i] = s; mini[i] = kg; }
            }
        }
    }

    // ---- cross-thread (tx) reduction per query ----------------------------
    __syncthreads();
    float* rv = smem;                         // [64][16]
    int*   ri = (int*)(smem + TM * 16);       // [64][16]
    #pragma unroll
    for (int i = 0; i < 4; i++) {
        int q = ty * 4 + i;
        rv[q * 16 + tx] = minv[i];
        ri[q * 16 + tx] = mini[i];
    }
    __syncthreads();
    if (tid < TM) {
        float bv = rv[tid * 16];
        int   bi = ri[tid * 16];
        #pragma unroll
        for (int t = 1; t < 16; t++) {
            float v  = rv[tid * 16 + t];
            int   ix = ri[tid * 16 + t];
            if (v < bv || (v == bv && ix < bi)) { bv = v; bi = ix; }
        }
        g_idx[n0 + tid] = bi;
    }
}

// ---------------------------------------------------------------------------
// Kernel 3: gather  out[b][c][h][w] = emb[idx[b*HW+hw]][c]
// gid == output linear index; consecutive lanes -> consecutive hw (coalesced
// out stores + coalesced idx loads; emb reads hit L2-resident 8.4 MB table).
// ---------------------------------------------------------------------------
__global__ void gather_kernel(const float* __restrict__ emb,
                              float* __restrict__ out) {
    int gid = blockIdx.x * blockDim.x + threadIdx.x;
    int hw  = gid & 1023;
    int c   = (gid >> 10) & 255;
    int b   = gid >> 18;
    int n   = (b << 10) | hw;
    out[gid] = emb[(size_t)g_idx[n] * C + c];
}

// ---------------------------------------------------------------------------
extern "C" void kernel_launch(void* const* d_in, const int* in_sizes, int n_in,
                              void* d_out, int out_size) {
    const float* z   = (const float*)d_in[0];   // [16,256,32,32]
    const float* emb = (const float*)d_in[1];   // [8192,256]
    float* out = (float*)d_out;                 // [16,256,32,32]

    static const size_t smem_bytes = (size_t)(C * TM + TN * C) * sizeof(float); // 128 KB
    cudaFuncSetAttribute(vq_argmin_kernel,
                         cudaFuncAttributeMaxDynamicSharedMemorySize,
                         (int)smem_bytes);

    enorm_kernel<<<K / 8, 256>>>(emb);
    vq_argmin_kernel<<<N / TM, 256, smem_bytes>>>(z, emb);
    gather_kernel<<<(N * C) / 256, 256>>>(emb, out);
}

// round 3
// speedup vs baseline: 1.0029x; 1.0014x over previous
#include <cuda_runtime.h>
#include <cuda_bf16.h>
#include <math_constants.h>

// Problem constants (from reference setup_inputs)
#define BQ  16
#define C   256
#define HW  1024          // 32*32
#define N   16384         // B*H*W
#define K   8192
#define TM  64            // query tile per block
#define TN  64            // code tile per k-iteration

// scratch: per-query argmin index, codebook row norms
__device__ int   g_idx[N];
__device__ float g_enorm[K];

// ---------------------------------------------------------------------------
// Kernel 1: ||e_k||^2 for all K codebook rows. One warp per row.
// ---------------------------------------------------------------------------
__global__ void enorm_kernel(const float* __restrict__ emb) {
    int k    = blockIdx.x * 8 + (threadIdx.x >> 5);
    int lane = threadIdx.x & 31;
    const float4* row = (const float4*)(emb + (size_t)k * C);
    float s = 0.f;
    #pragma unroll
    for (int i = 0; i < 2; i++) {
        float4 v = row[lane + 32 * i];
        s += v.x * v.x + v.y * v.y + v.z * v.z + v.w * v.w;
    }
    #pragma unroll
    for (int off = 16; off > 0; off >>= 1)
        s += __shfl_xor_sync(0xffffffffu, s, off);
    if (lane == 0) g_enorm[k] = s;
}

// ---------------------------------------------------------------------------
// Kernel 2: fused distance GEMM + argmin.
// Block: 256 threads (16x16). Block tile: 64 queries x 64 codes per k-iter,
// full C=256 in shared memory. Micro-tile 4x4 per thread.
//   zs_t : [C][TM]  z tile transposed (conflict-free stores & broadcast reads)
//   es   : [TN][C]  codebook tile, float4-XOR-swizzled for conflict-free reads
// Score = ||e||^2 - 2 z.e  (||z||^2 constant per row, irrelevant for argmin)
// ---------------------------------------------------------------------------
__global__ __launch_bounds__(256, 1)
void vq_argmin_kernel(const float* __restrict__ z,
                      const float* __restrict__ emb) {
    extern __shared__ float smem[];
    float* zs = smem;                 // C*TM floats (64 KB)
    float* es = smem + C * TM;        // TN*C floats (64 KB)

    const int tid = threadIdx.x;
    const int tx  = tid & 15;         // code micro-col  (codes 4*tx..4*tx+3)
    const int ty  = tid >> 4;         // query micro-row (queries 4*ty..4*ty+3)
    const int n0  = blockIdx.x * TM;

    // ---- load z tile, transposed to [c][q] --------------------------------
    {
        const int qq = tid & 63;
        const int cb = tid >> 6;      // 0..3
        const int n  = n0 + qq;
        const int b  = n >> 10;
        const int hw = n & 1023;
        const float* zb = z + (size_t)b * (C * HW) + hw;
        #pragma unroll 4
        for (int c0 = 0; c0 < C; c0 += 4) {
            int c = c0 + cb;
            zs[c * TM + qq] = zb[(size_t)c * HW];
        }
    }

    float minv[4];
    int   mini[4];
    #pragma unroll
    for (int i = 0; i < 4; i++) { minv[i] = CUDART_INF_F; mini[i] = 0; }

    const int sw = tx & 7;            // compute-side swizzle for this thread

    for (int k0 = 0; k0 < K; k0 += TN) {
        __syncthreads();              // es reuse barrier (also covers zs fill)

        // ---- load codebook tile, float4-swizzled --------------------------
        {
            const int c4  = tid & 63;
            const int kkb = tid >> 6;
            #pragma unroll
            for (int kk = kkb; kk < TN; kk += 4) {
                float4 v = *(const float4*)(emb + (size_t)(k0 + kk) * C + c4 * 4);
                int p = c4 ^ ((kk >> 2) & 7);
                *(float4*)(es + kk * C + p * 4) = v;
            }
        }
        __syncthreads();

        // ---- 64x64x256 micro-GEMM -----------------------------------------
        float acc[4][4] = {};
        #pragma unroll 2
        for (int c4 = 0; c4 < C / 4; c4++) {
            float4 aq[4];
            #pragma unroll
            for (int cc = 0; cc < 4; cc++)
                aq[cc] = *(const float4*)(zs + (c4 * 4 + cc) * TM + ty * 4);
            #pragma unroll
            for (int j = 0; j < 4; j++) {
                float4 bv = *(const float4*)(es + (4 * tx + j) * C + ((c4 ^ sw) << 2));
                acc[0][j] += aq[0].x * bv.x; acc[0][j] += aq[1].x * bv.y;
                acc[0][j] += aq[2].x * bv.z; acc[0][j] += aq[3].x * bv.w;
                acc[1][j] += aq[0].y * bv.x; acc[1][j] += aq[1].y * bv.y;
                acc[1][j] += aq[2].y * bv.z; acc[1][j] += aq[3].y * bv.w;
                acc[2][j] += aq[0].z * bv.x; acc[2][j] += aq[1].z * bv.y;
                acc[2][j] += aq[2].z * bv.z; acc[2][j] += aq[3].z * bv.w;
                acc[3][j] += aq[0].w * bv.x; acc[3][j] += aq[1].w * bv.y;
                acc[3][j] += aq[2].w * bv.z; acc[3][j] += aq[3].w * bv.w;
            }
        }

        // ---- running argmin (k ascending + strict < => first-min tiebreak)
        #pragma unroll
        for (int j = 0; j < 4; j++) {
            int kg = k0 + 4 * tx + j;
            float en = g_enorm[kg];
            #pragma unroll
            for (int i = 0; i < 4; i++) {
                float s = fmaf(-2.f, acc[i][j], en);
                if (s < minv[i]) { minv[i] = s; mini[i] = kg; }
            }
        }
    }

    // ---- cross-thread (tx) reduction per query ----------------------------
    __syncthreads();
    float* rv = smem;                         // [64][16]
    int*   ri = (int*)(smem + TM * 16);       // [64][16]
    #pragma unroll
    for (int i = 0; i < 4; i++) {
        int q = ty * 4 + i;
        rv[q * 16 + tx] = minv[i];
        ri[q * 16 + tx] = mini[i];
    }
    __syncthreads();
    if (tid < TM) {
        float bv = rv[tid * 16];
        int   bi = ri[tid * 16];
        #pragma unroll
        for (int t = 1; t < 16; t++) {
            float v  = rv[tid * 16 + t];
            int   ix = ri[tid * 16 + t];
            if (v < bv || (v == bv && ix < bi)) { bv = v; bi = ix; }
        }
        g_idx[n0 + tid] = bi;
    }
}

// ---------------------------------------------------------------------------
// Kernel 3: gather  out[b][c][h][w] = emb[idx[b*HW+hw]][c]
// gid == output linear index; consecutive lanes -> consecutive hw (coalesced
// out stores + coalesced idx loads; emb reads hit L2-resident 8.4 MB table).
// ---------------------------------------------------------------------------
__global__ void gather_kernel(const float* __restrict__ emb,
                              float* __restrict__ out) {
    int gid = blockIdx.x * blockDim.x + threadIdx.x;
    int hw  = gid & 1023;
    int c   = (gid >> 10) & 255;
    int b   = gid >> 18;
    int n   = (b << 10) | hw;
    out[gid] = emb[(size_t)g_idx[n] * C + c];
}

// ---------------------------------------------------------------------------
extern "C" void kernel_launch(void* const* d_in, const int* in_sizes, int n_in,
                              void* d_out, int out_size) {
    const float* z   = (const float*)d_in[0];   // [16,256,32,32]
    const float* emb = (const float*)d_in[1];   // [8192,256]
    float* out = (float*)d_out;                 // [16,256,32,32]

    static const size_t smem_bytes = (size_t)(C * TM + TN * C) * sizeof(float); // 128 KB
    cudaFuncSetAttribute(vq_argmin_kernel,
                         cudaFuncAttributeMaxDynamicSharedMemorySize,
                         (int)smem_bytes);

    enorm_kernel<<<K / 8, 256>>>(emb);
    vq_argmin_kernel<<<N / TM, 256, smem_bytes>>>(z, emb);
    gather_kernel<<<(N * C) / 256, 256>>>(emb, out);
}